// round 11
// baseline (speedup 1.0000x reference)
#include <cuda_runtime.h>

// Problem shape: B = 16384 rows, N = 64 neighbors, D = 64, H = 128
#define BROWS 16384

__device__ float g_C[BROWS * 128];     // [node_f | neigh_agg] per row
__device__ float g_AE[BROWS * 64];     // a = node_f @ W1 per row
// Classifier weight in tf32 B-fragment layout (tile kt 0..31, nt 0..15)
__device__ float2 g_WF[512 * 32];

typedef unsigned long long u64;
typedef unsigned int u32;

// ---------------- helpers ----------------
__device__ __forceinline__ float tanh_fast(float x) {
    float y; asm("tanh.approx.f32 %0, %1;" : "=f"(y) : "f"(x)); return y;
}
__device__ __forceinline__ u32 to_tf32(float x) {
    u32 r; asm("cvt.rna.tf32.f32 %0, %1;" : "=r"(r) : "f"(x)); return r;
}
// m16n8k8 tf32 MMA: D = A(16x8,row) * B(8x8,col) + D, fp32 accum
__device__ __forceinline__ void mma8(float* c, const u32* a, u32 b0, u32 b1) {
    asm("mma.sync.aligned.m16n8k8.row.col.f32.tf32.tf32.f32 "
        "{%0,%1,%2,%3}, {%4,%5,%6,%7}, {%8,%9}, {%0,%1,%2,%3};"
        : "+f"(c[0]), "+f"(c[1]), "+f"(c[2]), "+f"(c[3])
        : "r"(a[0]), "r"(a[1]), "r"(a[2]), "r"(a[3]), "r"(b0), "r"(b1));
}
__device__ __forceinline__ void bar_row(int row) {
    asm volatile("bar.sync %0, 64;" :: "r"(row + 1) : "memory");
}

// ---------------- SMEM layouts ----------------
#define FPITCH      68
// k_neigh
#define OFF_F       0                         // 2*64*68*4 = 34816
#define OFF_BF      34816                     // W2 B-fragments 16384
#define OFF_AE      51200                     // 512
#define OFF_WN      51712                     // 512
#define OFF_DT      52224                     // 512
#define OFF_MF      52736                     // 512
#define OFF_V       53248                     // 256
#define OFF_TW      53504
#define OFF_TB      53760
#define OFF_NW      54016
#define OFF_NB      54272
#define OFF_RED     54528                     // 32
#define NEIGH_SMEM  54560
// k_ae: W1 fragments 16384 + A tile 128*68*4 + params 1024
#define AE_SMEM     (16384 + 34816 + 1024)    // 52224
// k_gemm: A tile 64*68*4 + B fragments 4096*8
#define GEMM_SMEM   (64 * 68 * 4 + 4096 * 8)  // 50176

// ======== kernel A: node features -> g_C left half; aE = node_f@W1 =========
// grid 128 x 256 threads; CTA owns 128 rows. Also fills g_WF once.
__global__ __launch_bounds__(256)
void k_ae(const float* __restrict__ dt_node, const float* __restrict__ deg_node,
          const float* __restrict__ cc_node,
          const float* __restrict__ t2v_w, const float* __restrict__ t2v_b,
          const float* __restrict__ node_w, const float* __restrict__ node_b,
          const float* __restrict__ W1, const float* __restrict__ Wcls) {
    extern __shared__ __align__(16) char sm[];
    float2* sW1F = (float2*)sm;                 // 2048 float2
    float*  sA   = (float*)(sm + 16384);        // [128][68]
    float*  sTW  = (float*)(sm + 16384 + 34816);
    float*  sTB  = sTW + 64; float* sNW = sTB + 64; float* sNB = sNW + 64;

    const int t = threadIdx.x, lane = t & 31, wid = t >> 5;
    const int g = lane >> 2, tq = lane & 3;
    const int m0 = blockIdx.x * 128;

    // fill g_WF (classifier fragments) once, grid-stride
    for (int e = blockIdx.x * 256 + t; e < 512 * 32; e += gridDim.x * 256) {
        int tile = e >> 5, ln = e & 31;
        int kt = tile >> 4, nt = tile & 15;
        int gg = ln >> 2, tqq = ln & 3;
        const float* wr = Wcls + (nt * 8 + gg) * 256 + kt * 8 + tqq;
        float2 v;
        v.x = __uint_as_float(to_tf32(wr[0]));
        v.y = __uint_as_float(to_tf32(wr[4]));
        g_WF[e] = v;
    }
    // stage W1 fragments (B operand)
#pragma unroll
    for (int i = 0; i < 8; ++i) {
        int e = t + i * 256;                 // 0..2047
        int tile = e >> 5, ln = e & 31;
        int kt = tile >> 3, nt = tile & 7;
        int gg = ln >> 2, tqq = ln & 3;
        float2 v;
        v.x = __uint_as_float(to_tf32(W1[(kt * 8 + tqq) * 64 + nt * 8 + gg]));
        v.y = __uint_as_float(to_tf32(W1[(kt * 8 + tqq + 4) * 64 + nt * 8 + gg]));
        sW1F[tile * 32 + ln] = v;
    }
    if (t < 64) { sTW[t] = t2v_w[t]; sTB[t] = t2v_b[t];
                  sNW[t] = node_w[t]; sNB[t] = node_b[t]; }
    __syncthreads();

    // node features: 2 threads per row (halves of D)
    {
        const int r = t >> 1, h = t & 1, b = m0 + r;
        float tn  = fabsf(dt_node[b]);
        float dcn = deg_node[b] + cc_node[b];
        float f[32]; float s0 = 0.f, s1 = 0.f;
#pragma unroll
        for (int j = 0; j < 32; ++j) {
            int d = h * 32 + j;
            float vv = tn * sTW[d] + sTB[d];
            float cv = (d == 0) ? vv : __cosf(vv);
            float val = cv + dcn * sNW[d] + 2.0f * sNB[d];
            f[j] = val;
            if (j & 1) s1 += val * val; else s0 += val * val;
        }
        float ss = s0 + s1;
        ss += __shfl_xor_sync(0xffffffffu, ss, 1);
        float inv = rsqrtf(fmaxf(ss, 1e-24f));
        float* gc = g_C + b * 128 + h * 32;
        float* sa = sA + r * 68 + h * 32;
#pragma unroll
        for (int q = 0; q < 8; ++q) {
            float x0 = f[4 * q] * inv, x1 = f[4 * q + 1] * inv;
            float x2 = f[4 * q + 2] * inv, x3 = f[4 * q + 3] * inv;
            *(float4*)(gc + 4 * q) = make_float4(x0, x1, x2, x3);
            float4 w;
            w.x = __uint_as_float(to_tf32(x0)); w.y = __uint_as_float(to_tf32(x1));
            w.z = __uint_as_float(to_tf32(x2)); w.w = __uint_as_float(to_tf32(x3));
            *(float4*)(sa + 4 * q) = w;
        }
    }
    __syncthreads();

    // MMA: warp wid -> rows wid*16..+16, full N=64
    float acc[8][4];
#pragma unroll
    for (int nt = 0; nt < 8; ++nt)
#pragma unroll
        for (int c = 0; c < 4; ++c) acc[nt][c] = 0.f;

    const float* ap0 = sA + (wid * 16) * 68;
#pragma unroll
    for (int kt = 0; kt < 8; ++kt) {
        u32 a[4];
        const float* ap = ap0 + kt * 8;
        a[0] = __float_as_uint(ap[g * 68 + tq]);
        a[1] = __float_as_uint(ap[(g + 8) * 68 + tq]);
        a[2] = __float_as_uint(ap[g * 68 + tq + 4]);
        a[3] = __float_as_uint(ap[(g + 8) * 68 + tq + 4]);
#pragma unroll
        for (int nt = 0; nt < 8; ++nt) {
            float2 bb = sW1F[(kt * 8 + nt) * 32 + lane];
            mma8(acc[nt], a, __float_as_uint(bb.x), __float_as_uint(bb.y));
        }
    }
#pragma unroll
    for (int nt = 0; nt < 8; ++nt) {
        int rr = m0 + wid * 16 + g;
        int cc = nt * 8 + 2 * tq;
        *(float2*)(g_AE + rr * 64 + cc) = make_float2(acc[nt][0], acc[nt][1]);
        *(float2*)(g_AE + (rr + 8) * 64 + cc) = make_float2(acc[nt][2], acc[nt][3]);
    }
}

// ======== kernel B: persistent neighbor pipeline (2 rows/iter) ==============
__global__ __launch_bounds__(128, 4)
void k_neigh(const float* __restrict__ dt_neigh, const float* __restrict__ deg_neigh,
             const float* __restrict__ cc_neigh, const unsigned int* __restrict__ mask,
             const float* __restrict__ t2v_w, const float* __restrict__ t2v_b,
             const float* __restrict__ node_w, const float* __restrict__ node_b,
             const float* __restrict__ W2, const float* __restrict__ att_v,
             int pairs) {
    extern __shared__ __align__(16) char sm[];
    float*  sF  = (float*)(sm + OFF_F);
    float2* sBF = (float2*)(sm + OFF_BF);
    float*  sAE = (float*)(sm + OFF_AE);
    float*  sWn = (float*)(sm + OFF_WN);
    float*  sDT = (float*)(sm + OFF_DT);
    float*  sMF = (float*)(sm + OFF_MF);
    float*  sV  = (float*)(sm + OFF_V);
    float*  sTW = (float*)(sm + OFF_TW);
    float*  sTB = (float*)(sm + OFF_TB);
    float*  sNW = (float*)(sm + OFF_NW);
    float*  sNB = (float*)(sm + OFF_NB);
    float*  sRedM = (float*)(sm + OFF_RED);

    const int t = threadIdx.x;
    const int lane = t & 31, wid = t >> 5;
    const int row = t >> 6;
    const int dn  = t & 63;
    const int mrow = wid >> 1, mhalf = wid & 1;
    const int g = lane >> 2, tq = lane & 3;

    // one-time init: W2 -> B fragments (tf32), params
#pragma unroll
    for (int i = 0; i < 16; ++i) {
        int tile = wid * 16 + i;
        int kt = tile >> 3, nt = tile & 7;
        int d = kt * 8 + tq, e = nt * 8 + g;
        float2 v;
        v.x = __uint_as_float(to_tf32(W2[d * 64 + e]));
        v.y = __uint_as_float(to_tf32(W2[(d + 4) * 64 + e]));
        sBF[tile * 32 + lane] = v;
    }
    if (t < 64) { sV[t] = att_v[t]; sTW[t] = t2v_w[t]; sTB[t] = t2v_b[t];
                  sNW[t] = node_w[t]; sNB[t] = node_b[t]; }
    __syncthreads();

    // prefetch first iteration
    int p = blockIdx.x;
    float pv_dtn = 0.f, pv_dc = 0.f; u32 pv_mk = 0;
    {
        int b = p * 2 + row;
        pv_dtn = dt_neigh[b * 64 + dn];
        pv_dc  = deg_neigh[b * 64 + dn] + cc_neigh[b * 64 + dn];
        pv_mk  = mask[b * 64 + dn];
    }

    for (; p < pairs; p += gridDim.x) {
        const int b = p * 2 + row;
        const float c_dtn = pv_dtn, c_dc = pv_dc;
        const u32 c_mk = pv_mk;

        bar_row(row);   // guard: prev iter's aggregation (sF/sWn reads) done

        // ---- feature stage: thread (row, n=dn) ----
        float ae = g_AE[b * 64 + dn];          // issued early, covered by (B)
        const float mf = c_mk ? 1.0f : 0.0f;
        sDT[t] = c_dtn; sMF[t] = mf;
        float ms = mf;
#pragma unroll
        for (int off = 16; off > 0; off >>= 1)
            ms += __shfl_xor_sync(0xffffffffu, ms, off);
        if (lane == 0) sRedM[wid] = ms;
        {
            float ta = fabsf(c_dtn);
            float f[64]; float s0 = 0.f, s1 = 0.f, s2a = 0.f, s3 = 0.f;
#pragma unroll
            for (int d = 0; d < 64; d += 4) {
                float v0 = ta * sTW[d] + sTB[d];
                float v1 = ta * sTW[d + 1] + sTB[d + 1];
                float v2 = ta * sTW[d + 2] + sTB[d + 2];
                float v3 = ta * sTW[d + 3] + sTB[d + 3];
                float c0 = (d == 0) ? v0 : __cosf(v0);
                float c1 = __cosf(v1), c2 = __cosf(v2), c3 = __cosf(v3);
                float x0 = c0 + c_dc * sNW[d] + 2.0f * sNB[d];
                float x1 = c1 + c_dc * sNW[d + 1] + 2.0f * sNB[d + 1];
                float x2 = c2 + c_dc * sNW[d + 2] + 2.0f * sNB[d + 2];
                float x3 = c3 + c_dc * sNW[d + 3] + 2.0f * sNB[d + 3];
                f[d] = x0; f[d + 1] = x1; f[d + 2] = x2; f[d + 3] = x3;
                s0 += x0 * x0; s1 += x1 * x1; s2a += x2 * x2; s3 += x3 * x3;
            }
            float inv2 = rsqrtf(fmaxf((s0 + s1) + (s2a + s3), 1e-24f));
            float* frow = sF + (row * 64 + dn) * FPITCH;
#pragma unroll
            for (int q = 0; q < 16; ++q) {
                float4 v4;
                v4.x = __uint_as_float(to_tf32(f[4 * q + 0] * inv2));
                v4.y = __uint_as_float(to_tf32(f[4 * q + 1] * inv2));
                v4.z = __uint_as_float(to_tf32(f[4 * q + 2] * inv2));
                v4.w = __uint_as_float(to_tf32(f[4 * q + 3] * inv2));
                *(float4*)(frow + 4 * q) = v4;
            }
        }
        sAE[t] = ae;
        bar_row(row);   // (B) sF/sAE/sDT/sMF/sRedM visible

        // prefetch next iteration
        {
            int pn = p + gridDim.x;
            if (pn < pairs) {
                int bn = pn * 2 + row;
                pv_dtn = dt_neigh[bn * 64 + dn];
                pv_dc  = deg_neigh[bn * 64 + dn] + cc_neigh[bn * 64 + dn];
                pv_mk  = mask[bn * 64 + dn];
            }
        }
        const float rnin = 1.0f / fmaxf(sRedM[row * 2] + sRedM[row * 2 + 1], 1.0f);

        // ---- MMA: warp covers 32 neighbors (2 M-tiles) x 64 e x 64 d ----
        float cacc[2][8][4];
#pragma unroll
        for (int mt = 0; mt < 2; ++mt)
#pragma unroll
            for (int nt = 0; nt < 8; ++nt)
#pragma unroll
                for (int c = 0; c < 4; ++c) cacc[mt][nt][c] = 0.f;

        const float* fbase = sF + (mrow * 64 + mhalf * 32) * FPITCH;
#pragma unroll
        for (int kt = 0; kt < 8; ++kt) {
            u32 a[2][4];
#pragma unroll
            for (int mt = 0; mt < 2; ++mt) {
                const float* ap = fbase + mt * 16 * FPITCH + kt * 8;
                a[mt][0] = __float_as_uint(ap[g * FPITCH + tq]);
                a[mt][1] = __float_as_uint(ap[(g + 8) * FPITCH + tq]);
                a[mt][2] = __float_as_uint(ap[g * FPITCH + tq + 4]);
                a[mt][3] = __float_as_uint(ap[(g + 8) * FPITCH + tq + 4]);
            }
#pragma unroll
            for (int nt = 0; nt < 8; ++nt) {
                float2 bb = sBF[(kt * 8 + nt) * 32 + lane];
                u32 b0 = __float_as_uint(bb.x), b1 = __float_as_uint(bb.y);
                mma8(cacc[0][nt], a[0], b0, b1);
                mma8(cacc[1][nt], a[1], b0, b1);
            }
        }

        // ---- epilogue: att + score + w_n (fused) ----
        {
            const float* aE = sAE + mrow * 64;
            float attv[2][2] = {{0.f, 0.f}, {0.f, 0.f}};
#pragma unroll
            for (int nt = 0; nt < 8; ++nt) {
                float v0 = sV[nt * 8 + 2 * tq], v1 = sV[nt * 8 + 2 * tq + 1];
                float a0 = aE[nt * 8 + 2 * tq], a1 = aE[nt * 8 + 2 * tq + 1];
#pragma unroll
                for (int mt = 0; mt < 2; ++mt) {
                    attv[mt][0] += v0 * tanh_fast(a0 + cacc[mt][nt][0])
                                 + v1 * tanh_fast(a1 + cacc[mt][nt][1]);
                    attv[mt][1] += v0 * tanh_fast(a0 + cacc[mt][nt][2])
                                 + v1 * tanh_fast(a1 + cacc[mt][nt][3]);
                }
            }
#pragma unroll
            for (int mt = 0; mt < 2; ++mt)
#pragma unroll
                for (int r2 = 0; r2 < 2; ++r2) {
                    float x = attv[mt][r2];
                    x += __shfl_xor_sync(0xffffffffu, x, 1);
                    x += __shfl_xor_sync(0xffffffffu, x, 2);
                    if (tq == 0) {
                        int n = mhalf * 32 + mt * 16 + r2 * 8 + g;
                        float dtv = sDT[mrow * 64 + n];
                        float ts = 1.0f / (1.0f + 2.0f * dtv);
                        float ls = (ts > 0.f) ? ts : 0.01f * ts;
                        sWn[mrow * 64 + n] = sMF[mrow * 64 + n] * ls * x * rnin;
                    }
                }
        }
        bar_row(row);   // (E) sWn visible

        // ---- aggregation: thread (row, d=dn) -> g_C right half ----
        {
            float a0 = 0.f, a1 = 0.f, a2 = 0.f, a3 = 0.f;
            const float* fr = sF + row * 64 * FPITCH;
            const float* wn = sWn + row * 64;
#pragma unroll
            for (int n = 0; n < 64; n += 4) {
                a0 += wn[n]     * fr[n * FPITCH + dn];
                a1 += wn[n + 1] * fr[(n + 1) * FPITCH + dn];
                a2 += wn[n + 2] * fr[(n + 2) * FPITCH + dn];
                a3 += wn[n + 3] * fr[(n + 3) * FPITCH + dn];
            }
            g_C[b * 128 + 64 + dn] = (a0 + a1) + (a2 + a3);
        }
    }
}

// ======== kernel C: out = relu([g_C | hist] @ W^T), tf32 MMA ===============
// M=16384, N=128, K=256. CTA tile 64x128, BK=64, 256 threads (8 warps).
__global__ __launch_bounds__(256)
void k_gemm(const float* __restrict__ hist, float* __restrict__ out) {
    extern __shared__ __align__(16) float sg[];
    float* sA = sg;                        // [64][68]
    float2* sB = (float2*)(sg + 64 * 68);  // 128 tiles * 32 lanes per K-block

    const int m0 = blockIdx.x * 64;
    const int t = threadIdx.x;
    const int lane = t & 31, wid = t >> 5;
    const int mt_row = wid >> 1, nhalf = wid & 1;
    const int g = lane >> 2, tq = lane & 3;

    float acc[8][4];
#pragma unroll
    for (int nt = 0; nt < 8; ++nt)
#pragma unroll
        for (int c = 0; c < 4; ++c) acc[nt][c] = 0.f;

#pragma unroll
    for (int kb = 0; kb < 4; ++kb) {
        const float* src = (kb < 2) ? g_C : hist;
        const int koff = (kb & 1) * 64;
        __syncthreads();
#pragma unroll
        for (int i = 0; i < 4; ++i) {
            int s = t + i * 256;
            int r = s >> 4, k4 = (s & 15) * 4;
            float4 v = *(const float4*)(src + (m0 + r) * 128 + koff + k4);
            float4 w;
            w.x = __uint_as_float(to_tf32(v.x));
            w.y = __uint_as_float(to_tf32(v.y));
            w.z = __uint_as_float(to_tf32(v.z));
            w.w = __uint_as_float(to_tf32(v.w));
            *(float4*)(sA + r * 68 + k4) = w;
        }
        {
            const float4* wf = (const float4*)(g_WF + kb * 4096);
            float4* sb4 = (float4*)sB;
#pragma unroll
            for (int i = 0; i < 8; ++i) sb4[t + i * 256] = wf[t + i * 256];
        }
        __syncthreads();

#pragma unroll
        for (int ktl = 0; ktl < 8; ++ktl) {
            u32 a[4];
            const float* ap = sA + (mt_row * 16) * 68 + ktl * 8;
            a[0] = __float_as_uint(ap[g * 68 + tq]);
            a[1] = __float_as_uint(ap[(g + 8) * 68 + tq]);
            a[2] = __float_as_uint(ap[g * 68 + tq + 4]);
            a[3] = __float_as_uint(ap[(g + 8) * 68 + tq + 4]);
#pragma unroll
            for (int nt = 0; nt < 8; ++nt) {
                float2 bb = sB[(ktl * 16 + nhalf * 8 + nt) * 32 + lane];
                mma8(acc[nt], a, __float_as_uint(bb.x), __float_as_uint(bb.y));
            }
        }
    }

#pragma unroll
    for (int nt = 0; nt < 8; ++nt) {
        int r1 = m0 + mt_row * 16 + g;
        int cc = nhalf * 64 + nt * 8 + 2 * tq;
        float2 lo, hi;
        lo.x = fmaxf(acc[nt][0], 0.f); lo.y = fmaxf(acc[nt][1], 0.f);
        hi.x = fmaxf(acc[nt][2], 0.f); hi.y = fmaxf(acc[nt][3], 0.f);
        *(float2*)(out + r1 * 128 + cc) = lo;
        *(float2*)(out + (r1 + 8) * 128 + cc) = hi;
    }
}

// ---------------------------- launcher --------------------------------------
extern "C" void kernel_launch(void* const* d_in, const int* in_sizes, int n_in,
                              void* d_out, int out_size) {
    const float* dt_node   = (const float*)d_in[0];
    const float* deg_node  = (const float*)d_in[1];
    const float* cc_node   = (const float*)d_in[2];
    const float* dt_neigh  = (const float*)d_in[3];
    const float* deg_neigh = (const float*)d_in[4];
    const float* cc_neigh  = (const float*)d_in[5];
    const unsigned int* mask = (const unsigned int*)d_in[6];
    const float* hist      = (const float*)d_in[7];
    const float* t2v_w     = (const float*)d_in[8];
    const float* t2v_b     = (const float*)d_in[9];
    const float* node_w    = (const float*)d_in[10];
    const float* node_b    = (const float*)d_in[11];
    const float* att_W1    = (const float*)d_in[12];
    const float* att_W2    = (const float*)d_in[13];
    const float* att_v     = (const float*)d_in[14];
    const float* weight    = (const float*)d_in[15];
    float* out = (float*)d_out;

    const int B = in_sizes[0];   // 16384
    const int pairs = B / 2;

    static int smem_set = 0;
    if (!smem_set) {
        cudaFuncSetAttribute(k_ae, cudaFuncAttributeMaxDynamicSharedMemorySize,
                             AE_SMEM);
        cudaFuncSetAttribute(k_neigh, cudaFuncAttributeMaxDynamicSharedMemorySize,
                             NEIGH_SMEM);
        cudaFuncSetAttribute(k_gemm, cudaFuncAttributeMaxDynamicSharedMemorySize,
                             GEMM_SMEM);
        smem_set = 1;
    }

    k_ae<<<B / 128, 256, AE_SMEM>>>(dt_node, deg_node, cc_node,
                                    t2v_w, t2v_b, node_w, node_b,
                                    att_W1, weight);
    k_neigh<<<592, 128, NEIGH_SMEM>>>(dt_neigh, deg_neigh, cc_neigh, mask,
                                      t2v_w, t2v_b, node_w, node_b,
                                      att_W2, att_v, pairs);
    k_gemm<<<B / 64, 256, GEMM_SMEM>>>(hist, out);
}

// round 12
// speedup vs baseline: 1.3875x; 1.3875x over previous
#include <cuda_runtime.h>

// Problem shape: B = 16384 rows, N = 64 neighbors, D = 64, H = 128
#define BROWS 16384

__device__ float g_C[BROWS * 128];     // [node_f | neigh_agg] per row
// Classifier weight in tf32 B-fragment layout (tile kt 0..31, nt 0..15)
__device__ float2 g_WF[512 * 32];

typedef unsigned long long u64;
typedef unsigned int u32;

// ---------------- helpers ----------------
__device__ __forceinline__ float tanh_fast(float x) {
    float y; asm("tanh.approx.f32 %0, %1;" : "=f"(y) : "f"(x)); return y;
}
__device__ __forceinline__ u32 to_tf32(float x) {
    u32 r; asm("cvt.rna.tf32.f32 %0, %1;" : "=r"(r) : "f"(x)); return r;
}
// m16n8k8 tf32 MMA: D = A(16x8,row) * B(8x8,col) + D, fp32 accum
__device__ __forceinline__ void mma8(float* c, const u32* a, u32 b0, u32 b1) {
    asm("mma.sync.aligned.m16n8k8.row.col.f32.tf32.tf32.f32 "
        "{%0,%1,%2,%3}, {%4,%5,%6,%7}, {%8,%9}, {%0,%1,%2,%3};"
        : "+f"(c[0]), "+f"(c[1]), "+f"(c[2]), "+f"(c[3])
        : "r"(a[0]), "r"(a[1]), "r"(a[2]), "r"(a[3]), "r"(b0), "r"(b1));
}
// row-group barrier: syncs only the 2 warps owning `row`
__device__ __forceinline__ void bar_row(int row) {
    asm volatile("bar.sync %0, 64;" :: "r"(row + 1) : "memory");
}

// ---------------- SMEM layout for k_rows (dynamic, bytes) ----------------
#define FPITCH      68
#define OFF_F       0                         // 2*64*68*4 = 34816
#define OFF_BF      34816                     // W2 B-fragments 16384
#define OFF_W1      51200                     // 16384
#define OFF_NF      67584                     // 512  node_f [2][64]
#define OFF_AE      68096                     // 512  a = node_f@W1 [2][64]
#define OFF_WN      68608                     // 512  w_n [2][64]
#define OFF_DT      69120                     // 512  dt_neigh staged [2][64]
#define OFF_MF      69632                     // 512  mask staged [2][64]
#define OFF_V       70144                     // 256
#define OFF_TW      70400
#define OFF_TB      70656
#define OFF_NW      70912
#define OFF_NB      71168
#define OFF_RED     71424                     // 64 (norm[4] + mask[4])
#define SMEM_TOTAL  71488

// SMEM for k_gemm: A tile [64][68] floats + B fragments 4096 float2
#define GEMM_SMEM   (64 * 68 * 4 + 4096 * 8)  // 50176

// ---------------- kernel 1: persistent, 2 independent row pipelines --------
__global__ __launch_bounds__(128, 3)
void k_rows(const float* __restrict__ dt_node, const float* __restrict__ deg_node,
            const float* __restrict__ cc_node, const float* __restrict__ dt_neigh,
            const float* __restrict__ deg_neigh, const float* __restrict__ cc_neigh,
            const unsigned int* __restrict__ mask,
            const float* __restrict__ t2v_w, const float* __restrict__ t2v_b,
            const float* __restrict__ node_w, const float* __restrict__ node_b,
            const float* __restrict__ W1, const float* __restrict__ W2,
            const float* __restrict__ att_v, const float* __restrict__ Wcls,
            int pairs) {
    extern __shared__ __align__(16) char sm[];
    float* sF  = (float*)(sm + OFF_F);
    float2* sBF = (float2*)(sm + OFF_BF);
    float* sW1 = (float*)(sm + OFF_W1);
    float* sNF = (float*)(sm + OFF_NF);
    float* sAE = (float*)(sm + OFF_AE);
    float* sWn = (float*)(sm + OFF_WN);
    float* sDT = (float*)(sm + OFF_DT);
    float* sMF = (float*)(sm + OFF_MF);
    float* sV  = (float*)(sm + OFF_V);
    float* sTW = (float*)(sm + OFF_TW);
    float* sTB = (float*)(sm + OFF_TB);
    float* sNW = (float*)(sm + OFF_NW);
    float* sNB = (float*)(sm + OFF_NB);
    float* sRedN = (float*)(sm + OFF_RED);       // [4] norm partials
    float* sRedM = (float*)(sm + OFF_RED) + 4;   // [4] mask-count partials

    const int t = threadIdx.x;
    const int lane = t & 31, wid = t >> 5;
    const int row = t >> 6;        // which row of the pair (0/1)
    const int dn  = t & 63;        // dim / neighbor index
    const int mrow = wid >> 1, mhalf = wid & 1;
    const int g = lane >> 2, tq = lane & 3;

    // ---- fold-in: classifier weight -> tf32 B-fragment layout (once) ----
    for (int e = blockIdx.x * 128 + t; e < 512 * 32; e += gridDim.x * 128) {
        int tile = e >> 5, ln = e & 31;
        int kt = tile >> 4, nt = tile & 15;
        int gg = ln >> 2, tqq = ln & 3;
        const float* wr = Wcls + (nt * 8 + gg) * 256 + kt * 8 + tqq;
        float2 v;
        v.x = __uint_as_float(to_tf32(wr[0]));
        v.y = __uint_as_float(to_tf32(wr[4]));
        g_WF[e] = v;
    }

    // ---- one-time init ----
    {   // W1 plain [d][e]
        const float4* src = (const float4*)W1;
        float4* dst = (float4*)sW1;
#pragma unroll
        for (int i = 0; i < 8; ++i) dst[t + i * 128] = src[t + i * 128];
    }
    // W2 -> B fragments (tf32)
#pragma unroll
    for (int i = 0; i < 16; ++i) {
        int tile = wid * 16 + i;
        int kt = tile >> 3, nt = tile & 7;
        int d = kt * 8 + tq, e = nt * 8 + g;
        float2 v;
        v.x = __uint_as_float(to_tf32(W2[d * 64 + e]));
        v.y = __uint_as_float(to_tf32(W2[(d + 4) * 64 + e]));
        sBF[tile * 32 + lane] = v;
    }
    if (t < 64) { sV[t] = att_v[t]; sTW[t] = t2v_w[t]; sTB[t] = t2v_b[t];
                  sNW[t] = node_w[t]; sNB[t] = node_b[t]; }
    __syncthreads();

    // ---- prefetch first iteration's inputs ----
    int p = blockIdx.x;
    float pv_tn = 0.f, pv_dcn = 0.f, pv_dtn = 0.f, pv_dc = 0.f;
    u32 pv_mk = 0;
    {
        int b = p * 2 + row;
        pv_tn  = fabsf(dt_node[b]);
        pv_dcn = deg_node[b] + cc_node[b];
        pv_dtn = dt_neigh[b * 64 + dn];
        pv_dc  = deg_neigh[b * 64 + dn] + cc_neigh[b * 64 + dn];
        pv_mk  = mask[b * 64 + dn];
    }

    for (; p < pairs; p += gridDim.x) {
        const int b = p * 2 + row;
        const float c_tn = pv_tn, c_dcn = pv_dcn;
        const float c_dtn = pv_dtn, c_dc = pv_dc;
        const u32 c_mk = pv_mk;

        // ---- node feature partial + mask count: thread (row, d=dn) ----
        float vv0 = c_tn * sTW[dn] + sTB[dn];
        float fb  = ((dn == 0) ? vv0 : __cosf(vv0)) + c_dcn * sNW[dn] + 2.0f * sNB[dn];
        float ss = fb * fb;
        float ms = c_mk ? 1.0f : 0.0f;
        const float mf = ms;
#pragma unroll
        for (int off = 16; off > 0; off >>= 1) {
            ss += __shfl_xor_sync(0xffffffffu, ss, off);
            ms += __shfl_xor_sync(0xffffffffu, ms, off);
        }
        if (lane == 0) { sRedN[wid] = ss; sRedM[wid] = ms; }
        bar_row(row);                                      // (A) + sF/sWn guard
        float inv = rsqrtf(fmaxf(sRedN[row * 2] + sRedN[row * 2 + 1], 1e-24f));
        const float rnin = 1.0f /
            fmaxf(sRedM[row * 2] + sRedM[row * 2 + 1], 1.0f);
        sNF[t] = fb * inv;
        sDT[t] = c_dtn;
        sMF[t] = mf;

        // ---- neighbor feature: thread (row, n=dn) -> sF (tf32-rounded) ----
        {
            float ta = fabsf(c_dtn);
            float f[64]; float s0 = 0.f, s1 = 0.f, s2a = 0.f, s3 = 0.f;
#pragma unroll
            for (int d = 0; d < 64; d += 4) {
                float v0 = ta * sTW[d] + sTB[d];
                float v1 = ta * sTW[d + 1] + sTB[d + 1];
                float v2 = ta * sTW[d + 2] + sTB[d + 2];
                float v3 = ta * sTW[d + 3] + sTB[d + 3];
                float c0 = (d == 0) ? v0 : __cosf(v0);
                float c1 = __cosf(v1), c2 = __cosf(v2), c3 = __cosf(v3);
                float x0 = c0 + c_dc * sNW[d] + 2.0f * sNB[d];
                float x1 = c1 + c_dc * sNW[d + 1] + 2.0f * sNB[d + 1];
                float x2 = c2 + c_dc * sNW[d + 2] + 2.0f * sNB[d + 2];
                float x3 = c3 + c_dc * sNW[d + 3] + 2.0f * sNB[d + 3];
                f[d] = x0; f[d + 1] = x1; f[d + 2] = x2; f[d + 3] = x3;
                s0 += x0 * x0; s1 += x1 * x1; s2a += x2 * x2; s3 += x3 * x3;
            }
            float inv2 = rsqrtf(fmaxf((s0 + s1) + (s2a + s3), 1e-24f));
            float* frow = sF + (row * 64 + dn) * FPITCH;
#pragma unroll
            for (int q = 0; q < 16; ++q) {
                float4 v4;
                v4.x = __uint_as_float(to_tf32(f[4 * q + 0] * inv2));
                v4.y = __uint_as_float(to_tf32(f[4 * q + 1] * inv2));
                v4.z = __uint_as_float(to_tf32(f[4 * q + 2] * inv2));
                v4.w = __uint_as_float(to_tf32(f[4 * q + 3] * inv2));
                *(float4*)(frow + 4 * q) = v4;
            }
        }
        bar_row(row);                                      // (B) sNF/sF/sDT/sMF

        // ---- prefetch next iteration ----
        {
            int pn = p + gridDim.x;
            if (pn < pairs) {
                int bn = pn * 2 + row;
                pv_tn  = fabsf(dt_node[bn]);
                pv_dcn = deg_node[bn] + cc_node[bn];
                pv_dtn = dt_neigh[bn * 64 + dn];
                pv_dc  = deg_neigh[bn * 64 + dn] + cc_neigh[bn * 64 + dn];
                pv_mk  = mask[bn * 64 + dn];
            }
        }

        // ---- a[e] = node_f . W1[:,e]: thread (row, e=dn) ----
        {
            float a0 = 0.f, a1 = 0.f, a2 = 0.f, a3 = 0.f;
            const float* nf = sNF + row * 64;
#pragma unroll
            for (int d = 0; d < 64; d += 4) {
                a0 += nf[d]     * sW1[d * 64 + dn];
                a1 += nf[d + 1] * sW1[(d + 1) * 64 + dn];
                a2 += nf[d + 2] * sW1[(d + 2) * 64 + dn];
                a3 += nf[d + 3] * sW1[(d + 3) * 64 + dn];
            }
            sAE[t] = (a0 + a1) + (a2 + a3);
        }
        bar_row(row);                                      // (C) sAE visible

        // ---- MMA: warp covers 32 neighbors (2 M-tiles) x 64 e x 64 d ----
        float cacc[2][8][4];
#pragma unroll
        for (int mt = 0; mt < 2; ++mt)
#pragma unroll
            for (int nt = 0; nt < 8; ++nt)
#pragma unroll
                for (int c = 0; c < 4; ++c) cacc[mt][nt][c] = 0.f;

        const float* fbase = sF + (mrow * 64 + mhalf * 32) * FPITCH;
#pragma unroll
        for (int kt = 0; kt < 8; ++kt) {
            u32 a[2][4];
#pragma unroll
            for (int mt = 0; mt < 2; ++mt) {
                const float* ap = fbase + mt * 16 * FPITCH + kt * 8;
                a[mt][0] = __float_as_uint(ap[g * FPITCH + tq]);
                a[mt][1] = __float_as_uint(ap[(g + 8) * FPITCH + tq]);
                a[mt][2] = __float_as_uint(ap[g * FPITCH + tq + 4]);
                a[mt][3] = __float_as_uint(ap[(g + 8) * FPITCH + tq + 4]);
            }
#pragma unroll
            for (int nt = 0; nt < 8; ++nt) {
                float2 bb = sBF[(kt * 8 + nt) * 32 + lane];
                u32 b0 = __float_as_uint(bb.x), b1 = __float_as_uint(bb.y);
                mma8(cacc[0][nt], a[0], b0, b1);
                mma8(cacc[1][nt], a[1], b0, b1);
            }
        }

        // ---- fused epilogue: att -> score -> w_n directly ----
        {
            const float* aE = sAE + mrow * 64;
            float attv[2][2] = {{0.f, 0.f}, {0.f, 0.f}};
#pragma unroll
            for (int nt = 0; nt < 8; ++nt) {
                float v0 = sV[nt * 8 + 2 * tq], v1 = sV[nt * 8 + 2 * tq + 1];
                float a0 = aE[nt * 8 + 2 * tq], a1 = aE[nt * 8 + 2 * tq + 1];
#pragma unroll
                for (int mt = 0; mt < 2; ++mt) {
                    attv[mt][0] += v0 * tanh_fast(a0 + cacc[mt][nt][0])
                                 + v1 * tanh_fast(a1 + cacc[mt][nt][1]);
                    attv[mt][1] += v0 * tanh_fast(a0 + cacc[mt][nt][2])
                                 + v1 * tanh_fast(a1 + cacc[mt][nt][3]);
                }
            }
#pragma unroll
            for (int mt = 0; mt < 2; ++mt)
#pragma unroll
                for (int r2 = 0; r2 < 2; ++r2) {
                    float x = attv[mt][r2];
                    x += __shfl_xor_sync(0xffffffffu, x, 1);
                    x += __shfl_xor_sync(0xffffffffu, x, 2);
                    if (tq == 0) {
                        int n = mhalf * 32 + mt * 16 + r2 * 8 + g;
                        float dtv = sDT[mrow * 64 + n];
                        float ts = 1.0f / (1.0f + 2.0f * dtv);   // Decayer
                        float ls = (ts > 0.f) ? ts : 0.01f * ts; // leaky_relu
                        sWn[mrow * 64 + n] = sMF[mrow * 64 + n] * ls * x * rnin;
                    }
                }
        }
        bar_row(row);                                      // (D) sWn visible

        // ---- aggregation: thread (row, d=dn) ----
        {
            float a0 = 0.f, a1 = 0.f, a2 = 0.f, a3 = 0.f;
            const float* fr = sF + row * 64 * FPITCH;
            const float* wn = sWn + row * 64;
#pragma unroll
            for (int n = 0; n < 64; n += 4) {
                a0 += wn[n]     * fr[n * FPITCH + dn];
                a1 += wn[n + 1] * fr[(n + 1) * FPITCH + dn];
                a2 += wn[n + 2] * fr[(n + 2) * FPITCH + dn];
                a3 += wn[n + 3] * fr[(n + 3) * FPITCH + dn];
            }
            g_C[b * 128 + dn] = sNF[t];
            g_C[b * 128 + 64 + dn] = (a0 + a1) + (a2 + a3);
        }
        // barrier (A) of next iteration guards sF/sNF/sWn reuse
    }
}

// ---------------- kernel 2: out = relu([g_C | hist] @ W^T), tf32 MMA -------
// M=16384, N=128, K=256. CTA tile 64x128, BK=64, 256 threads (8 warps).
__global__ __launch_bounds__(256)
void k_gemm(const float* __restrict__ hist, float* __restrict__ out) {
    extern __shared__ __align__(16) float sg[];
    float* sA = sg;                        // [64][68]
    float2* sB = (float2*)(sg + 64 * 68);  // 128 tiles * 32 lanes per K-block

    const int m0 = blockIdx.x * 64;
    const int t = threadIdx.x;
    const int lane = t & 31, wid = t >> 5;
    const int mt_row = wid >> 1, nhalf = wid & 1;
    const int g = lane >> 2, tq = lane & 3;

    float acc[8][4];
#pragma unroll
    for (int nt = 0; nt < 8; ++nt)
#pragma unroll
        for (int c = 0; c < 4; ++c) acc[nt][c] = 0.f;

#pragma unroll
    for (int kb = 0; kb < 4; ++kb) {
        const float* src = (kb < 2) ? g_C : hist;
        const int koff = (kb & 1) * 64;
        __syncthreads();
#pragma unroll
        for (int i = 0; i < 4; ++i) {
            int s = t + i * 256;
            int r = s >> 4, k4 = (s & 15) * 4;
            float4 v = *(const float4*)(src + (m0 + r) * 128 + koff + k4);
            float4 w;
            w.x = __uint_as_float(to_tf32(v.x));
            w.y = __uint_as_float(to_tf32(v.y));
            w.z = __uint_as_float(to_tf32(v.z));
            w.w = __uint_as_float(to_tf32(v.w));
            *(float4*)(sA + r * 68 + k4) = w;
        }
        {
            const float4* wf = (const float4*)(g_WF + kb * 4096);
            float4* sb4 = (float4*)sB;
#pragma unroll
            for (int i = 0; i < 8; ++i) sb4[t + i * 256] = wf[t + i * 256];
        }
        __syncthreads();

#pragma unroll
        for (int ktl = 0; ktl < 8; ++ktl) {
            u32 a[4];
            const float* ap = sA + (mt_row * 16) * 68 + ktl * 8;
            a[0] = __float_as_uint(ap[g * 68 + tq]);
            a[1] = __float_as_uint(ap[(g + 8) * 68 + tq]);
            a[2] = __float_as_uint(ap[g * 68 + tq + 4]);
            a[3] = __float_as_uint(ap[(g + 8) * 68 + tq + 4]);
#pragma unroll
            for (int nt = 0; nt < 8; ++nt) {
                float2 bb = sB[(ktl * 16 + nhalf * 8 + nt) * 32 + lane];
                mma8(acc[nt], a, __float_as_uint(bb.x), __float_as_uint(bb.y));
            }
        }
    }

#pragma unroll
    for (int nt = 0; nt < 8; ++nt) {
        int r1 = m0 + mt_row * 16 + g;
        int cc = nhalf * 64 + nt * 8 + 2 * tq;
        float2 lo, hi;
        lo.x = fmaxf(acc[nt][0], 0.f); lo.y = fmaxf(acc[nt][1], 0.f);
        hi.x = fmaxf(acc[nt][2], 0.f); hi.y = fmaxf(acc[nt][3], 0.f);
        *(float2*)(out + r1 * 128 + cc) = lo;
        *(float2*)(out + (r1 + 8) * 128 + cc) = hi;
    }
}

// ---------------------------- launcher --------------------------------------
extern "C" void kernel_launch(void* const* d_in, const int* in_sizes, int n_in,
                              void* d_out, int out_size) {
    const float* dt_node   = (const float*)d_in[0];
    const float* deg_node  = (const float*)d_in[1];
    const float* cc_node   = (const float*)d_in[2];
    const float* dt_neigh  = (const float*)d_in[3];
    const float* deg_neigh = (const float*)d_in[4];
    const float* cc_neigh  = (const float*)d_in[5];
    const unsigned int* mask = (const unsigned int*)d_in[6];
    const float* hist      = (const float*)d_in[7];
    const float* t2v_w     = (const float*)d_in[8];
    const float* t2v_b     = (const float*)d_in[9];
    const float* node_w    = (const float*)d_in[10];
    const float* node_b    = (const float*)d_in[11];
    const float* att_W1    = (const float*)d_in[12];
    const float* att_W2    = (const float*)d_in[13];
    const float* att_v     = (const float*)d_in[14];
    const float* weight    = (const float*)d_in[15];
    float* out = (float*)d_out;

    const int B = in_sizes[0];   // 16384
    const int pairs = B / 2;

    static int smem_set = 0;
    if (!smem_set) {
        cudaFuncSetAttribute(k_rows, cudaFuncAttributeMaxDynamicSharedMemorySize,
                             SMEM_TOTAL);
        cudaFuncSetAttribute(k_gemm, cudaFuncAttributeMaxDynamicSharedMemorySize,
                             GEMM_SMEM);
        smem_set = 1;
    }

    k_rows<<<444, 128, SMEM_TOTAL>>>(dt_node, deg_node, cc_node, dt_neigh,
                                     deg_neigh, cc_neigh, mask, t2v_w, t2v_b,
                                     node_w, node_b, att_W1, att_W2, att_v,
                                     weight, pairs);
    k_gemm<<<B / 64, 256, GEMM_SMEM>>>(hist, out);
}